// round 3
// baseline (speedup 1.0000x reference)
#include <cuda_runtime.h>

#define NPTS     16384
#define THREADS  256
#define QPT      4                     // queries per thread
#define QPB      (THREADS * QPT)       // 1024 queries per block
#define QBLOCKS  (NPTS / QPB)          // 16 query-blocks per direction
#define NSLICES  9
#define SLICE    1824                  // 9 * 1824 = 16416 >= 16384

// Per-query running min, stored as order-preserving unsigned keys.
__device__ unsigned int g_min[2 * NPTS];

__global__ void init_kernel() {
    int i = blockIdx.x * blockDim.x + threadIdx.x;
    if (i < 2 * NPTS) g_min[i] = 0xFFFFFFFFu;  // max key = identity for min
}

// Order-preserving float -> unsigned key (total order incl. negatives).
__device__ __forceinline__ unsigned int fkey(float f) {
    int b = __float_as_int(f);
    return (unsigned int)(b ^ ((b >> 31) | 0x80000000));
}

__global__ __launch_bounds__(THREADS)
void chamfer_kernel(const float* __restrict__ gt, const float* __restrict__ gen) {
    __shared__ float s_bx[SLICE], s_by[SLICE], s_bz[SLICE], s_bn[SLICE];

    const int sliceIdx = blockIdx.x % NSLICES;
    const int dq       = blockIdx.x / NSLICES;   // 0..31
    const int dir      = dq / QBLOCKS;           // 0: gt->gen, 1: gen->gt
    const int qb       = dq % QBLOCKS;

    const float* __restrict__ A = dir ? gen : gt;
    const float* __restrict__ B = dir ? gt  : gen;

    // Fill smem with transformed B slice: (-2bx, -2by, -2bz, |b|^2)
    const int s0 = sliceIdx * SLICE;
    for (int i = threadIdx.x; i < SLICE; i += THREADS) {
        int j = s0 + i;
        if (j < NPTS) {
            float bx = B[3 * j], by = B[3 * j + 1], bz = B[3 * j + 2];
            s_bx[i] = -2.0f * bx;
            s_by[i] = -2.0f * by;
            s_bz[i] = -2.0f * bz;
            s_bn[i] = bx * bx + by * by + bz * bz;
        } else {
            s_bx[i] = 0.0f; s_by[i] = 0.0f; s_bz[i] = 0.0f;
            s_bn[i] = 3.0e38f;   // padding: never the min
        }
    }

    // Load this thread's QPT query points (coalesced stride-THREADS layout)
    float ax[QPT], ay[QPT], az[QPT], m[QPT];
    const int qbase = qb * QPB + threadIdx.x;
    #pragma unroll
    for (int k = 0; k < QPT; k++) {
        int q = qbase + k * THREADS;
        ax[k] = A[3 * q];
        ay[k] = A[3 * q + 1];
        az[k] = A[3 * q + 2];
        m[k]  = 3.0e38f;
    }
    __syncthreads();

    // Main loop: per B-point, 4 broadcast LDS + QPT*3 FFMA + QPT FMNMX
    #pragma unroll 4
    for (int j = 0; j < SLICE; j++) {
        float bx = s_bx[j], by = s_by[j], bz = s_bz[j], bn = s_bn[j];
        #pragma unroll
        for (int k = 0; k < QPT; k++) {
            float d = fmaf(ax[k], bx, fmaf(ay[k], by, fmaf(az[k], bz, bn)));
            m[k] = fminf(m[k], d);
        }
    }

    // Combine across slices via atomicMin on ordered keys; add |a|^2 now.
    #pragma unroll
    for (int k = 0; k < QPT; k++) {
        int q = qbase + k * THREADS;
        float na = fmaf(ax[k], ax[k], fmaf(ay[k], ay[k], az[k] * az[k]));
        atomicMin(&g_min[dir * NPTS + q], fkey(m[k] + na));
    }
}

__global__ void reduce_kernel(float* __restrict__ out) {
    __shared__ float ssum[1024];
    float s = 0.0f;
    for (int i = threadIdx.x; i < 2 * NPTS; i += 1024) {
        unsigned int k = g_min[i];
        int b = (k & 0x80000000u) ? (int)(k ^ 0x80000000u) : ~(int)k;
        s += __int_as_float(b);
    }
    ssum[threadIdx.x] = s;
    __syncthreads();
    for (int off = 512; off > 0; off >>= 1) {
        if (threadIdx.x < off) ssum[threadIdx.x] += ssum[threadIdx.x + off];
        __syncthreads();
    }
    // result = mean(min_gt) + mean(min_gen) = (sum of all mins) / NPTS
    if (threadIdx.x == 0) out[0] = ssum[0] / (float)NPTS;
}

extern "C" void kernel_launch(void* const* d_in, const int* in_sizes, int n_in,
                              void* d_out, int out_size) {
    const float* gt  = (const float*)d_in[0];
    const float* gen = (const float*)d_in[1];
    float* out = (float*)d_out;

    init_kernel<<<(2 * NPTS + 255) / 256, 256>>>();
    chamfer_kernel<<<2 * QBLOCKS * NSLICES, THREADS>>>(gt, gen);
    reduce_kernel<<<1, 1024>>>(out);
}

// round 4
// speedup vs baseline: 1.2837x; 1.2837x over previous
#include <cuda_runtime.h>

#define NPTS     16384
#define THREADS  256
#define QPT      8                     // queries per thread
#define QPB      (THREADS * QPT)       // 2048 queries per block
#define QBLOCKS  (NPTS / QPB)          // 8 query-blocks per direction
#define NSLICES  18
#define SLICE    912                   // even; 18 * 912 = 16416 >= 16384
#define SLICE2   (SLICE / 2)

typedef unsigned long long u64;

// Per-(slice, direction, query) partial mins. Plain stores -> no init kernel.
__device__ float g_part[NSLICES * 2 * NPTS];
__device__ float g_bsum[32];

__device__ __forceinline__ u64 pack2(float x) {
    u64 r; asm("mov.b64 %0, {%1, %1};" : "=l"(r) : "f"(x)); return r;
}
__device__ __forceinline__ u64 fma2(u64 a, u64 b, u64 c) {
    u64 d; asm("fma.rn.f32x2 %0, %1, %2, %3;" : "=l"(d) : "l"(a), "l"(b), "l"(c));
    return d;
}
__device__ __forceinline__ void unpack2(u64 v, float& lo, float& hi) {
    asm("mov.b64 {%0, %1}, %2;" : "=f"(lo), "=f"(hi) : "l"(v));
}

__global__ __launch_bounds__(THREADS)
void chamfer_kernel(const float* __restrict__ gt, const float* __restrict__ gen) {
    // B slice, transformed: (-2bx, -2by, -2bz, |b|^2). Adjacent pairs feed LDS.64.
    __shared__ __align__(16) float s_bx[SLICE], s_by[SLICE], s_bz[SLICE], s_bn[SLICE];

    const int sliceIdx = blockIdx.x % NSLICES;
    const int dq       = blockIdx.x / NSLICES;   // 0..15
    const int dir      = dq / QBLOCKS;           // 0: gt->gen, 1: gen->gt
    const int qb       = dq % QBLOCKS;

    const float* __restrict__ A = dir ? gen : gt;
    const float* __restrict__ B = dir ? gt  : gen;

    const int s0 = sliceIdx * SLICE;
    for (int i = threadIdx.x; i < SLICE; i += THREADS) {
        int j = s0 + i;
        if (j < NPTS) {
            float bx = B[3 * j], by = B[3 * j + 1], bz = B[3 * j + 2];
            s_bx[i] = -2.0f * bx;
            s_by[i] = -2.0f * by;
            s_bz[i] = -2.0f * bz;
            s_bn[i] = bx * bx + by * by + bz * bz;
        } else {
            s_bx[i] = 0.0f; s_by[i] = 0.0f; s_bz[i] = 0.0f;
            s_bn[i] = 3.0e38f;   // padding: never the min
        }
    }

    // Load this thread's QPT query points; pack broadcast pairs once.
    u64 axx[QPT], ayy[QPT], azz[QPT];
    float na[QPT], mlo[QPT], mhi[QPT];
    const int qbase = qb * QPB + threadIdx.x;
    #pragma unroll
    for (int k = 0; k < QPT; k++) {
        int q = qbase + k * THREADS;
        float ax = A[3 * q], ay = A[3 * q + 1], az = A[3 * q + 2];
        axx[k] = pack2(ax); ayy[k] = pack2(ay); azz[k] = pack2(az);
        na[k]  = fmaf(ax, ax, fmaf(ay, ay, az * az));
        mlo[k] = 3.0e38f;  mhi[k] = 3.0e38f;
    }
    __syncthreads();

    const u64* __restrict__ bx2 = (const u64*)s_bx;
    const u64* __restrict__ by2 = (const u64*)s_by;
    const u64* __restrict__ bz2 = (const u64*)s_bz;
    const u64* __restrict__ bn2 = (const u64*)s_bn;

    // Main loop: per B-pair, 4 LDS.64 + QPT*3 FFMA2 (fma pipe) + QPT*2 FMNMX (alu pipe)
    #pragma unroll 2
    for (int jp = 0; jp < SLICE2; jp++) {
        u64 bx = bx2[jp], by = by2[jp], bz = bz2[jp], bn = bn2[jp];
        #pragma unroll
        for (int k = 0; k < QPT; k++) {
            u64 d = fma2(axx[k], bx, fma2(ayy[k], by, fma2(azz[k], bz, bn)));
            float lo, hi; unpack2(d, lo, hi);
            mlo[k] = fminf(mlo[k], lo);
            mhi[k] = fminf(mhi[k], hi);
        }
    }

    // Store per-slice partial mins (plain STG; reduce kernel does the cross-slice min)
    float* __restrict__ part = g_part + sliceIdx * (2 * NPTS) + dir * NPTS;
    #pragma unroll
    for (int k = 0; k < QPT; k++) {
        int q = qbase + k * THREADS;
        part[q] = fminf(mlo[k], mhi[k]) + na[k];
    }
}

// Stage 1: 32 blocks x 256 threads. Each block covers 1024 (dir,query) slots:
// min over NSLICES partials, then block-sum.
__global__ __launch_bounds__(256)
void reduce1_kernel() {
    __shared__ float ssum[256];
    float s = 0.0f;
    #pragma unroll
    for (int r = 0; r < 4; r++) {
        int idx = blockIdx.x * 1024 + r * 256 + threadIdx.x;
        float m = 3.0e38f;
        #pragma unroll
        for (int sl = 0; sl < NSLICES; sl++)
            m = fminf(m, g_part[sl * (2 * NPTS) + idx]);
        s += m;
    }
    ssum[threadIdx.x] = s;
    __syncthreads();
    for (int off = 128; off > 0; off >>= 1) {
        if (threadIdx.x < off) ssum[threadIdx.x] += ssum[threadIdx.x + off];
        __syncthreads();
    }
    if (threadIdx.x == 0) g_bsum[blockIdx.x] = ssum[0];
}

// Stage 2: one warp, deterministic shfl tree.
__global__ void reduce2_kernel(float* __restrict__ out) {
    float s = g_bsum[threadIdx.x];
    #pragma unroll
    for (int off = 16; off > 0; off >>= 1)
        s += __shfl_xor_sync(0xFFFFFFFFu, s, off);
    // result = mean(min_gt) + mean(min_gen) = (sum of all mins) / NPTS
    if (threadIdx.x == 0) out[0] = s / (float)NPTS;
}

extern "C" void kernel_launch(void* const* d_in, const int* in_sizes, int n_in,
                              void* d_out, int out_size) {
    const float* gt  = (const float*)d_in[0];
    const float* gen = (const float*)d_in[1];
    float* out = (float*)d_out;

    chamfer_kernel<<<2 * QBLOCKS * NSLICES, THREADS>>>(gt, gen);
    reduce1_kernel<<<32, 256>>>();
    reduce2_kernel<<<1, 32>>>(out);
}

// round 5
// speedup vs baseline: 1.3142x; 1.0238x over previous
#include <cuda_runtime.h>

#define NPTS     16384
#define THREADS  256
#define QPT      8                     // queries per thread
#define QPB      (THREADS * QPT)       // 2048 queries per block
#define QBLOCKS  (NPTS / QPB)          // 8 query-blocks per direction
#define NSLICES  36
#define SLICE    456                   // even; 36 * 456 = 16416 >= 16384
#define SLICE2   (SLICE / 2)           // 228, divisible by 4

typedef unsigned long long u64;

// Per-(slice, direction, query) partial mins. Plain stores -> no init kernel.
__device__ float g_part[NSLICES * 2 * NPTS];
__device__ float g_bsum[32];

__device__ __forceinline__ u64 pack2(float x) {
    u64 r; asm("mov.b64 %0, {%1, %1};" : "=l"(r) : "f"(x)); return r;
}
__device__ __forceinline__ u64 fma2(u64 a, u64 b, u64 c) {
    u64 d; asm("fma.rn.f32x2 %0, %1, %2, %3;" : "=l"(d) : "l"(a), "l"(b), "l"(c));
    return d;
}
__device__ __forceinline__ void unpack2(u64 v, float& lo, float& hi) {
    asm("mov.b64 {%0, %1}, %2;" : "=f"(lo), "=f"(hi) : "l"(v));
}

__global__ __launch_bounds__(THREADS, 4)
void chamfer_kernel(const float* __restrict__ gt, const float* __restrict__ gen) {
    // B slice, transformed: (-2bx, -2by, -2bz, |b|^2). Adjacent pairs feed LDS.64.
    __shared__ __align__(16) float s_bx[SLICE], s_by[SLICE], s_bz[SLICE], s_bn[SLICE];

    const int sliceIdx = blockIdx.x % NSLICES;
    const int dq       = blockIdx.x / NSLICES;   // 0..15
    const int dir      = dq / QBLOCKS;           // 0: gt->gen, 1: gen->gt
    const int qb       = dq % QBLOCKS;

    const float* __restrict__ A = dir ? gen : gt;
    const float* __restrict__ B = dir ? gt  : gen;

    const int s0 = sliceIdx * SLICE;
    for (int i = threadIdx.x; i < SLICE; i += THREADS) {
        int j = s0 + i;
        if (j < NPTS) {
            float bx = B[3 * j], by = B[3 * j + 1], bz = B[3 * j + 2];
            s_bx[i] = -2.0f * bx;
            s_by[i] = -2.0f * by;
            s_bz[i] = -2.0f * bz;
            s_bn[i] = bx * bx + by * by + bz * bz;
        } else {
            s_bx[i] = 0.0f; s_by[i] = 0.0f; s_bz[i] = 0.0f;
            s_bn[i] = 3.0e38f;   // padding: never the min
        }
    }

    // Load this thread's QPT query points; pack broadcast pairs once.
    u64 axx[QPT], ayy[QPT], azz[QPT];
    float na[QPT], mlo[QPT], mhi[QPT];
    const int qbase = qb * QPB + threadIdx.x;
    #pragma unroll
    for (int k = 0; k < QPT; k++) {
        int q = qbase + k * THREADS;
        float ax = A[3 * q], ay = A[3 * q + 1], az = A[3 * q + 2];
        axx[k] = pack2(ax); ayy[k] = pack2(ay); azz[k] = pack2(az);
        na[k]  = fmaf(ax, ax, fmaf(ay, ay, az * az));
        mlo[k] = 3.0e38f;  mhi[k] = 3.0e38f;
    }
    __syncthreads();

    const u64* __restrict__ bx2 = (const u64*)s_bx;
    const u64* __restrict__ by2 = (const u64*)s_by;
    const u64* __restrict__ bz2 = (const u64*)s_bz;
    const u64* __restrict__ bn2 = (const u64*)s_bn;

    // Main loop: per B-pair, 4 LDS.64 + QPT*3 FFMA2 (fma pipe) + QPT*2 FMNMX (alu pipe)
    #pragma unroll 4
    for (int jp = 0; jp < SLICE2; jp++) {
        u64 bx = bx2[jp], by = by2[jp], bz = bz2[jp], bn = bn2[jp];
        #pragma unroll
        for (int k = 0; k < QPT; k++) {
            u64 d = fma2(axx[k], bx, fma2(ayy[k], by, fma2(azz[k], bz, bn)));
            float lo, hi; unpack2(d, lo, hi);
            mlo[k] = fminf(mlo[k], lo);
            mhi[k] = fminf(mhi[k], hi);
        }
    }

    // Store per-slice partial mins (plain STG; reduce kernel does the cross-slice min)
    float* __restrict__ part = g_part + sliceIdx * (2 * NPTS) + dir * NPTS;
    #pragma unroll
    for (int k = 0; k < QPT; k++) {
        int q = qbase + k * THREADS;
        part[q] = fminf(mlo[k], mhi[k]) + na[k];
    }
}

// Stage 1: 32 blocks x 256 threads. Each block covers 1024 (dir,query) slots:
// min over NSLICES partials, then block-sum.
__global__ __launch_bounds__(256)
void reduce1_kernel() {
    __shared__ float ssum[256];
    float s = 0.0f;
    #pragma unroll
    for (int r = 0; r < 4; r++) {
        int idx = blockIdx.x * 1024 + r * 256 + threadIdx.x;
        float m = 3.0e38f;
        #pragma unroll
        for (int sl = 0; sl < NSLICES; sl++)
            m = fminf(m, g_part[sl * (2 * NPTS) + idx]);
        s += m;
    }
    ssum[threadIdx.x] = s;
    __syncthreads();
    for (int off = 128; off > 0; off >>= 1) {
        if (threadIdx.x < off) ssum[threadIdx.x] += ssum[threadIdx.x + off];
        __syncthreads();
    }
    if (threadIdx.x == 0) g_bsum[blockIdx.x] = ssum[0];
}

// Stage 2: one warp, deterministic shfl tree.
__global__ void reduce2_kernel(float* __restrict__ out) {
    float s = g_bsum[threadIdx.x];
    #pragma unroll
    for (int off = 16; off > 0; off >>= 1)
        s += __shfl_xor_sync(0xFFFFFFFFu, s, off);
    // result = mean(min_gt) + mean(min_gen) = (sum of all mins) / NPTS
    if (threadIdx.x == 0) out[0] = s / (float)NPTS;
}

extern "C" void kernel_launch(void* const* d_in, const int* in_sizes, int n_in,
                              void* d_out, int out_size) {
    const float* gt  = (const float*)d_in[0];
    const float* gen = (const float*)d_in[1];
    float* out = (float*)d_out;

    chamfer_kernel<<<2 * QBLOCKS * NSLICES, THREADS>>>(gt, gen);
    reduce1_kernel<<<32, 256>>>();
    reduce2_kernel<<<1, 32>>>(out);
}

// round 7
// speedup vs baseline: 1.4548x; 1.1070x over previous
#include <cuda_runtime.h>

#define NPTS     16384
#define THREADS  256
#define QPT      4                     // queries per thread
#define QPB      (THREADS * QPT)       // 1024 queries per block
#define QBLOCKS  (NPTS / QPB)          // 16 query-blocks per direction
#define NSLICES  18
#define SLICE    912                   // even; 18 * 912 = 16416 >= 16384
#define SLICE2   (SLICE / 2)           // 456, divisible by 4

typedef unsigned long long u64;

// Per-(slice, direction, query) partial mins. Plain stores -> no init kernel.
__device__ float g_part[NSLICES * 2 * NPTS];
__device__ float g_bsum[32];

__device__ __forceinline__ u64 pack2(float x) {
    u64 r; asm("mov.b64 %0, {%1, %1};" : "=l"(r) : "f"(x)); return r;
}
__device__ __forceinline__ u64 fma2(u64 a, u64 b, u64 c) {
    u64 d; asm("fma.rn.f32x2 %0, %1, %2, %3;" : "=l"(d) : "l"(a), "l"(b), "l"(c));
    return d;
}
__device__ __forceinline__ void unpack2(u64 v, float& lo, float& hi) {
    asm("mov.b64 {%0, %1}, %2;" : "=f"(lo), "=f"(hi) : "l"(v));
}

__global__ __launch_bounds__(THREADS, 4)
void chamfer_kernel(const float* __restrict__ gt, const float* __restrict__ gen) {
    // B slice, transformed: (-2bx, -2by, -2bz, |b|^2). Adjacent pairs feed LDS.64.
    __shared__ __align__(16) float s_bx[SLICE], s_by[SLICE], s_bz[SLICE], s_bn[SLICE];

    const int sliceIdx = blockIdx.x % NSLICES;
    const int dq       = blockIdx.x / NSLICES;   // 0..31
    const int dir      = dq / QBLOCKS;           // 0: gt->gen, 1: gen->gt
    const int qb       = dq % QBLOCKS;

    const float* __restrict__ A = dir ? gen : gt;
    const float* __restrict__ B = dir ? gt  : gen;

    const int s0 = sliceIdx * SLICE;
    for (int i = threadIdx.x; i < SLICE; i += THREADS) {
        int j = s0 + i;
        if (j < NPTS) {
            float bx = B[3 * j], by = B[3 * j + 1], bz = B[3 * j + 2];
            s_bx[i] = -2.0f * bx;
            s_by[i] = -2.0f * by;
            s_bz[i] = -2.0f * bz;
            s_bn[i] = bx * bx + by * by + bz * bz;
        } else {
            s_bx[i] = 0.0f; s_by[i] = 0.0f; s_bz[i] = 0.0f;
            s_bn[i] = 3.0e38f;   // padding: never the min
        }
    }

    // Load this thread's QPT query points; pack broadcast pairs once.
    u64 axx[QPT], ayy[QPT], azz[QPT];
    float na[QPT], mlo[QPT], mhi[QPT];
    const int qbase = qb * QPB + threadIdx.x;
    #pragma unroll
    for (int k = 0; k < QPT; k++) {
        int q = qbase + k * THREADS;
        float ax = A[3 * q], ay = A[3 * q + 1], az = A[3 * q + 2];
        axx[k] = pack2(ax); ayy[k] = pack2(ay); azz[k] = pack2(az);
        na[k]  = fmaf(ax, ax, fmaf(ay, ay, az * az));
        mlo[k] = 3.0e38f;  mhi[k] = 3.0e38f;
    }
    __syncthreads();

    const u64* __restrict__ bx2 = (const u64*)s_bx;
    const u64* __restrict__ by2 = (const u64*)s_by;
    const u64* __restrict__ bz2 = (const u64*)s_bz;
    const u64* __restrict__ bn2 = (const u64*)s_bn;

    // Main loop: per B-pair, 4 LDS.64 + QPT*3 FFMA2 (fma pipe) + QPT*2 FMNMX (alu pipe)
    #pragma unroll 4
    for (int jp = 0; jp < SLICE2; jp++) {
        u64 bx = bx2[jp], by = by2[jp], bz = bz2[jp], bn = bn2[jp];
        #pragma unroll
        for (int k = 0; k < QPT; k++) {
            u64 d = fma2(axx[k], bx, fma2(ayy[k], by, fma2(azz[k], bz, bn)));
            float lo, hi; unpack2(d, lo, hi);
            mlo[k] = fminf(mlo[k], lo);
            mhi[k] = fminf(mhi[k], hi);
        }
    }

    // Store per-slice partial mins (plain STG; reduce kernel does the cross-slice min)
    float* __restrict__ part = g_part + sliceIdx * (2 * NPTS) + dir * NPTS;
    #pragma unroll
    for (int k = 0; k < QPT; k++) {
        int q = qbase + k * THREADS;
        part[q] = fminf(mlo[k], mhi[k]) + na[k];
    }
}

// Stage 1: 32 blocks x 256 threads. Each block covers 1024 (dir,query) slots:
// min over NSLICES partials, then block-sum.
__global__ __launch_bounds__(256)
void reduce1_kernel() {
    __shared__ float ssum[256];
    float s = 0.0f;
    #pragma unroll
    for (int r = 0; r < 4; r++) {
        int idx = blockIdx.x * 1024 + r * 256 + threadIdx.x;
        float m = 3.0e38f;
        #pragma unroll
        for (int sl = 0; sl < NSLICES; sl++)
            m = fminf(m, g_part[sl * (2 * NPTS) + idx]);
        s += m;
    }
    ssum[threadIdx.x] = s;
    __syncthreads();
    for (int off = 128; off > 0; off >>= 1) {
        if (threadIdx.x < off) ssum[threadIdx.x] += ssum[threadIdx.x + off];
        __syncthreads();
    }
    if (threadIdx.x == 0) g_bsum[blockIdx.x] = ssum[0];
}

// Stage 2: one warp, deterministic shfl tree.
__global__ void reduce2_kernel(float* __restrict__ out) {
    float s = g_bsum[threadIdx.x];
    #pragma unroll
    for (int off = 16; off > 0; off >>= 1)
        s += __shfl_xor_sync(0xFFFFFFFFu, s, off);
    // result = mean(min_gt) + mean(min_gen) = (sum of all mins) / NPTS
    if (threadIdx.x == 0) out[0] = s / (float)NPTS;
}

extern "C" void kernel_launch(void* const* d_in, const int* in_sizes, int n_in,
                              void* d_out, int out_size) {
    const float* gt  = (const float*)d_in[0];
    const float* gen = (const float*)d_in[1];
    float* out = (float*)d_out;

    chamfer_kernel<<<2 * QBLOCKS * NSLICES, THREADS>>>(gt, gen);
    reduce1_kernel<<<32, 256>>>();
    reduce2_kernel<<<1, 32>>>(out);
}